// round 8
// baseline (speedup 1.0000x reference)
#include <cuda_runtime.h>
#include <cuda_fp16.h>
#include <cstdint>

#define V_TOTAL 1497600
#define E_TOTAL 4492800
#define BATCH   256
#define VPM     5850
#define K2DIM   58500   /* VPM*10 */
#define KH      (K2DIM / 2)
#define NOUT    64
#define NEG     0.01f

// ---------------- scratch ----------------
// 16B row per vertex: {h2(x,y), h2(z,1), h2(sum_x,sum_y), h2(sum_z,deg)}
__device__ uint4  g_va[V_TOTAL];
// 32B row per vertex: [2v] = x1 f16 {x0x1,x2x3,x4|deg,0}, [2v+1] = sb sums (same packing)
__device__ uint4  g_xb[V_TOTAL * 2];
__device__ unsigned g_yh2[(size_t)V_TOTAL * 5];   // fc1 out f16, h2 pairs along k
__device__ unsigned g_w2h2[(size_t)NOUT * KH];    // fc2 weights f16, h2 pairs along k
__device__ float  g_acc[BATCH * NOUT];            // fc2 split-K accumulator

// ---------------- helpers ----------------
__device__ __forceinline__ void red_add_h8(uint4* addr, uint4 v) {
    asm volatile("red.global.add.noftz.v4.f16x2 [%0], {%1,%2,%3,%4};"
                 :: "l"(addr), "r"(v.x), "r"(v.y), "r"(v.z), "r"(v.w) : "memory");
}
__device__ __forceinline__ void red_add_h4(uint2* addr, uint2 v) {
    asm volatile("red.global.add.noftz.v2.f16x2 [%0], {%1,%2};"
                 :: "l"(addr), "r"(v.x), "r"(v.y) : "memory");
}
__device__ __forceinline__ void red_add_f2(float* addr, float a, float b) {
    asm volatile("red.global.add.v2.f32 [%0], {%1,%2};"
                 :: "l"(addr), "f"(a), "f"(b) : "memory");
}
__device__ __forceinline__ float leaky(float t) { return t >= 0.f ? t : NEG * t; }

typedef unsigned long long u64t;
__device__ __forceinline__ u64t pk2(float a, float b) {
    u64t r; asm("mov.b64 %0,{%1,%2};" : "=l"(r) : "f"(a), "f"(b)); return r;
}
__device__ __forceinline__ void fma2(u64t& a, u64t x, u64t y) {
    asm("fma.rn.f32x2 %0,%1,%2,%0;" : "+l"(a) : "l"(x), "l"(y));
}
__device__ __forceinline__ void upk2(u64t d, float& a, float& b) {
    asm("mov.b64 {%0,%1},%2;" : "=f"(a), "=f"(b) : "l"(d));
}
__device__ __forceinline__ unsigned h2u(__half2 h) { return *reinterpret_cast<unsigned*>(&h); }
__device__ __forceinline__ float2 u2f2(unsigned u) {
    __half2 h = *reinterpret_cast<__half2*>(&u);
    return __half22float2(h);
}

// ---------------- K0: build f16 verts (+zeroed sums) in one row; zero g_acc ----------------
__global__ void k_prep(const float* __restrict__ verts) {
    int i = blockIdx.x * blockDim.x + threadIdx.x;
    int stride = gridDim.x * blockDim.x;
    for (int v = i; v < V_TOTAL; v += stride) {
        float x = verts[3 * v + 0], y = verts[3 * v + 1], z = verts[3 * v + 2];
        g_va[v] = make_uint4(h2u(__floats2half2_rn(x, y)), h2u(__floats2half2_rn(z, 1.f)), 0u, 0u);
    }
    if (i < BATCH * NOUT) g_acc[i] = 0.f;
}

// ---------------- K0b: convert fc2 weights to f16 h2-pairs ----------------
__global__ void k_w2h(const float* __restrict__ w2) {
    int i = blockIdx.x * blockDim.x + threadIdx.x;
    if (i >= NOUT * KH) return;
    float2 f = *(const float2*)(w2 + 2 * (size_t)i);
    g_w2h2[i] = h2u(__floats2half2_rn(f.x, f.y));
}

// ---------------- K1: scatter verts+degree (f16; gather & red share the row) ----------------
__global__ void k_scatter_a(const int2* __restrict__ edges) {
    int e = blockIdx.x * blockDim.x + threadIdx.x;
    if (e >= E_TOTAL) return;
    int2 ij = __ldcs(edges + e);
    uint2 vi = __ldg((const uint2*)&g_va[ij.x]);
    uint2 vj = __ldg((const uint2*)&g_va[ij.y]);
    red_add_h4(((uint2*)&g_va[ij.x]) + 1, vj);
    red_add_h4(((uint2*)&g_va[ij.y]) + 1, vi);
}

// ---------------- K2: x1 = leaky(...) -> f16 rows; zero sb half ----------------
__global__ void k_x1(const float* __restrict__ verts,
                     const float* __restrict__ w0a, const float* __restrict__ b0a,
                     const float* __restrict__ w1a, const float* __restrict__ b1a) {
    int v = blockIdx.x * blockDim.x + threadIdx.x;
    if (v >= V_TOTAL) return;
    float p0 = verts[3 * v + 0], p1 = verts[3 * v + 1], p2 = verts[3 * v + 2];
    uint4 vr = g_va[v];
    float2 sxy = u2f2(vr.z), szd = u2f2(vr.w);   // {sum_x,sum_y},{sum_z,degree}
    float o[5];
#pragma unroll
    for (int m = 0; m < 5; m++) {
        float t = __ldg(b0a + m) + szd.y * __ldg(b1a + m);
        t += p0 * __ldg(w0a + 3 * m + 0) + p1 * __ldg(w0a + 3 * m + 1) + p2 * __ldg(w0a + 3 * m + 2);
        t += sxy.x * __ldg(w1a + 3 * m + 0) + sxy.y * __ldg(w1a + 3 * m + 1) + szd.x * __ldg(w1a + 3 * m + 2);
        o[m] = leaky(t);
    }
    uint4 row;
    row.x = h2u(__floats2half2_rn(o[0], o[1]));
    row.y = h2u(__floats2half2_rn(o[2], o[3]));
    row.z = h2u(__floats2half2_rn(o[4], szd.y));   // degree rides along
    row.w = 0u;
    g_xb[2 * v + 0] = row;
    g_xb[2 * v + 1] = make_uint4(0u, 0u, 0u, 0u);
}

// ---------------- K3: scatter x1 (f16; gather & red share the 32B sector) ----------------
__global__ void k_scatter_b(const int2* __restrict__ edges) {
    int e = blockIdx.x * blockDim.x + threadIdx.x;
    if (e >= E_TOTAL) return;
    int2 ij = __ldcs(edges + e);
    uint4 xi = __ldg(g_xb + 2 * ij.x);
    uint4 xj = __ldg(g_xb + 2 * ij.y);
    red_add_h8(g_xb + 2 * ij.x + 1, xj);
    red_add_h8(g_xb + 2 * ij.y + 1, xi);
}

// ---------------- K4: fused layer-b + fc1, packed f32x2, f16 output ----------------
__global__ __launch_bounds__(256)
void k_vertex(const float* __restrict__ w0b, const float* __restrict__ b0b,
              const float* __restrict__ w1b, const float* __restrict__ b1b,
              const float* __restrict__ fc1w, const float* __restrict__ fc1b) {
    __shared__ u64t s_w0d[100], s_w1d[100], s_b0d[20], s_b1d[20], s_f1d[200];
    __shared__ float s_f1b[16];
    int tid = threadIdx.x;
    if (tid < 100) { float a = w0b[tid], b = w1b[tid]; s_w0d[tid] = pk2(a, a); s_w1d[tid] = pk2(b, b); }
    if (tid < 20)  { float a = b0b[tid], b = b1b[tid]; s_b0d[tid] = pk2(a, a); s_b1d[tid] = pk2(b, b); }
    if (tid < 200) { float f = fc1w[tid]; s_f1d[tid] = pk2(f, f); }
    if (tid < 10)  s_f1b[tid] = fc1b[tid];
    __syncthreads();

    int base = (blockIdx.x * blockDim.x + threadIdx.x) * 4;
    if (base >= V_TOTAL) return;   // V_TOTAL % 4 == 0

    float x1[4][5], sb[4][5], deg[4];
#pragma unroll
    for (int u = 0; u < 4; u++) {
        int v = base + u;
        uint4 xr = g_xb[2 * v];
        float2 f;
        f = u2f2(xr.x); x1[u][0] = f.x; x1[u][1] = f.y;
        f = u2f2(xr.y); x1[u][2] = f.x; x1[u][3] = f.y;
        f = u2f2(xr.z); x1[u][4] = f.x; deg[u] = f.y;
        uint4 srr = g_xb[2 * v + 1];
        f = u2f2(srr.x); sb[u][0] = f.x; sb[u][1] = f.y;
        f = u2f2(srr.y); sb[u][2] = f.x; sb[u][3] = f.y;
        f = u2f2(srr.z); sb[u][4] = f.x;
    }
    u64t x1p[2][5], sbp[2][5], degp[2];
#pragma unroll
    for (int m = 0; m < 5; m++) {
        x1p[0][m] = pk2(x1[0][m], x1[1][m]); x1p[1][m] = pk2(x1[2][m], x1[3][m]);
        sbp[0][m] = pk2(sb[0][m], sb[1][m]); sbp[1][m] = pk2(sb[2][m], sb[3][m]);
    }
    degp[0] = pk2(deg[0], deg[1]); degp[1] = pk2(deg[2], deg[3]);

    u64t yac[10][2];
#pragma unroll
    for (int q = 0; q < 10; q++) {
        float bq = s_f1b[q];
        yac[q][0] = pk2(bq, bq);
        yac[q][1] = pk2(bq, bq);
    }

#pragma unroll
    for (int n = 0; n < 20; n++) {
        u64t t0 = s_b0d[n], t1 = t0;
        u64t b1d = s_b1d[n];
        fma2(t0, degp[0], b1d);
        fma2(t1, degp[1], b1d);
#pragma unroll
        for (int m = 0; m < 5; m++) {
            u64t w0 = s_w0d[5 * n + m], w1 = s_w1d[5 * n + m];
            fma2(t0, x1p[0][m], w0); fma2(t0, sbp[0][m], w1);
            fma2(t1, x1p[1][m], w0); fma2(t1, sbp[1][m], w1);
        }
        float a, b, c, d;
        upk2(t0, a, b); upk2(t1, c, d);
        u64t xp0 = pk2(leaky(a), leaky(b));
        u64t xp1 = pk2(leaky(c), leaky(d));
#pragma unroll
        for (int q = 0; q < 10; q++) {
            u64t fw2 = s_f1d[20 * q + n];
            fma2(yac[q][0], xp0, fw2);
            fma2(yac[q][1], xp1, fw2);
        }
    }

    float yf[40];
#pragma unroll
    for (int q = 0; q < 10; q++) {
        float a, b;
        upk2(yac[q][0], a, b); yf[q] = leaky(a); yf[10 + q] = leaky(b);
        upk2(yac[q][1], a, b); yf[20 + q] = leaky(a); yf[30 + q] = leaky(b);
    }
    unsigned yo2[20];
#pragma unroll
    for (int t = 0; t < 20; t++) yo2[t] = h2u(__floats2half2_rn(yf[2 * t], yf[2 * t + 1]));
    uint4* dst = (uint4*)(g_yh2 + (size_t)base * 5);   // base%4==0 -> 16B aligned
#pragma unroll
    for (int t = 0; t < 5; t++)
        dst[t] = make_uint4(yo2[4 * t], yo2[4 * t + 1], yo2[4 * t + 2], yo2[4 * t + 3]);
}

// ---------------- K5: fc2 via mma.sync m16n8k16 f16->f32, k-split, red epilogue ----------------
#define KS 148
__global__ __launch_bounds__(256)
void k_fc2mma() {
    const int steps_total = (K2DIM + 15) / 16;          // 3657
    const int per = (steps_total + KS - 1) / KS;        // 25
    int s0 = blockIdx.x * per;
    int s1 = min(s0 + per, steps_total);

    int tid = threadIdx.x;
    int warp = tid >> 5, l = tid & 31;
    int m0 = warp * 32;                                 // 8 warps cover M=256
    int r = l >> 2, c0 = (l & 3) * 2;

    float acc[2][8][4];
#pragma unroll
    for (int mt = 0; mt < 2; mt++)
#pragma unroll
        for (int nt = 0; nt < 8; nt++)
#pragma unroll
            for (int q = 0; q < 4; q++) acc[mt][nt][q] = 0.f;

    const unsigned* ya = g_yh2;
    const unsigned* wa = g_w2h2;

    for (int s = s0; s < s1; s++) {
        int k0 = s * 16;
        int kc = k0 + c0;
        bool g0 = kc < K2DIM;           // pair-safe (kc even, K2DIM even)
        bool g1 = kc + 8 < K2DIM;
        int h0 = kc >> 1, h1 = (kc + 8) >> 1;

        unsigned a[2][4];
#pragma unroll
        for (int mt = 0; mt < 2; mt++) {
            size_t rowA = (size_t)(m0 + mt * 16 + r) * KH;
            size_t rowB = rowA + (size_t)8 * KH;
            a[mt][0] = g0 ? __ldg(ya + rowA + h0) : 0u;
            a[mt][1] = g0 ? __ldg(ya + rowB + h0) : 0u;
            a[mt][2] = g1 ? __ldg(ya + rowA + h1) : 0u;
            a[mt][3] = g1 ? __ldg(ya + rowB + h1) : 0u;
        }
        unsigned b[8][2];
#pragma unroll
        for (int nt = 0; nt < 8; nt++) {
            size_t rowN = (size_t)(nt * 8 + r) * KH;
            b[nt][0] = g0 ? __ldg(wa + rowN + h0) : 0u;
            b[nt][1] = g1 ? __ldg(wa + rowN + h1) : 0u;
        }
#pragma unroll
        for (int mt = 0; mt < 2; mt++)
#pragma unroll
            for (int nt = 0; nt < 8; nt++) {
                asm volatile(
                    "mma.sync.aligned.m16n8k16.row.col.f32.f16.f16.f32 "
                    "{%0,%1,%2,%3}, {%4,%5,%6,%7}, {%8,%9}, {%0,%1,%2,%3};"
                    : "+f"(acc[mt][nt][0]), "+f"(acc[mt][nt][1]),
                      "+f"(acc[mt][nt][2]), "+f"(acc[mt][nt][3])
                    : "r"(a[mt][0]), "r"(a[mt][1]), "r"(a[mt][2]), "r"(a[mt][3]),
                      "r"(b[nt][0]), "r"(b[nt][1]));
            }
    }

    if (s0 >= s1) return;
#pragma unroll
    for (int mt = 0; mt < 2; mt++)
#pragma unroll
        for (int nt = 0; nt < 8; nt++) {
            int row = m0 + mt * 16 + r;
            int col = nt * 8 + c0;
            red_add_f2(&g_acc[row * NOUT + col], acc[mt][nt][0], acc[mt][nt][1]);
            red_add_f2(&g_acc[(row + 8) * NOUT + col], acc[mt][nt][2], acc[mt][nt][3]);
        }
}

// ---------------- K6: bias + softmax ----------------
__global__ void k_softmax(const float* __restrict__ fc2b, float* __restrict__ out) {
    int b = blockIdx.x * 8 + (threadIdx.x >> 5);
    int lane = threadIdx.x & 31;
    if (b >= BATCH) return;
    float v0 = g_acc[b * 64 + lane]      + __ldg(fc2b + lane);
    float v1 = g_acc[b * 64 + 32 + lane] + __ldg(fc2b + 32 + lane);
    float m = fmaxf(v0, v1);
#pragma unroll
    for (int o = 16; o; o >>= 1) m = fmaxf(m, __shfl_xor_sync(0xffffffffu, m, o));
    float e0 = expf(v0 - m), e1 = expf(v1 - m);
    float s = e0 + e1;
#pragma unroll
    for (int o = 16; o; o >>= 1) s += __shfl_xor_sync(0xffffffffu, s, o);
    float inv = 1.f / s;
    out[b * 64 + lane]      = e0 * inv;
    out[b * 64 + 32 + lane] = e1 * inv;
}

// ---------------- launch ----------------
extern "C" void kernel_launch(void* const* d_in, const int* in_sizes, int n_in,
                              void* d_out, int out_size) {
    const float* verts = (const float*)d_in[0];
    const int2*  edges = (const int2*)d_in[1];
    const float* w0a  = (const float*)d_in[2];
    const float* b0a  = (const float*)d_in[3];
    const float* w1a  = (const float*)d_in[4];
    const float* b1a  = (const float*)d_in[5];
    const float* w0b  = (const float*)d_in[6];
    const float* b0b  = (const float*)d_in[7];
    const float* w1b  = (const float*)d_in[8];
    const float* b1b  = (const float*)d_in[9];
    const float* fc1w = (const float*)d_in[10];
    const float* fc1b = (const float*)d_in[11];
    const float* fc2w = (const float*)d_in[12];
    const float* fc2b = (const float*)d_in[13];

    k_prep<<<4096, 256>>>(verts);
    k_w2h<<<(NOUT * KH + 255) / 256, 256>>>(fc2w);
    k_scatter_a<<<(E_TOTAL + 255) / 256, 256>>>(edges);
    k_x1<<<(V_TOTAL + 255) / 256, 256>>>(verts, w0a, b0a, w1a, b1a);
    k_scatter_b<<<(E_TOTAL + 255) / 256, 256>>>(edges);
    k_vertex<<<(V_TOTAL / 4 + 255) / 256, 256>>>(w0b, b0b, w1b, b1b, fc1w, fc1b);
    k_fc2mma<<<KS, 256>>>();
    k_softmax<<<32, 256>>>(fc2b, (float*)d_out);
}

// round 9
// speedup vs baseline: 1.6367x; 1.6367x over previous
#include <cuda_runtime.h>
#include <cuda_fp16.h>
#include <cstdint>

#define V_TOTAL 1497600
#define E_TOTAL 4492800
#define BATCH   256
#define VPM     5850
#define K2DIM   58500   /* VPM*10 */
#define KH      (K2DIM / 2)
#define NOUT    64
#define NEG     0.01f

// ---------------- scratch (R7 separate-array layout) ----------------
__device__ uint2  g_vph[V_TOTAL];           // verts f16: {h2(x,y), h2(z,1)}
__device__ uint2  g_sah[V_TOTAL];           // layer-a sums f16: {h2(sx,sy), h2(sz,deg)}
__device__ uint4  g_x1h[V_TOTAL];           // x1 f16: {x0,x1},{x2,x3},{x4,deg},{0,0}
__device__ uint4  g_sbh[V_TOTAL];           // layer-b sums f16, same packing
__device__ unsigned g_yh2[(size_t)V_TOTAL * 5];   // fc1 out f16, h2 pairs along k
__device__ unsigned g_w2h2[(size_t)NOUT * KH];    // fc2 weights f16, h2 pairs along k
__device__ float  g_acc[BATCH * NOUT];            // fc2 split-K accumulator

// ---------------- helpers ----------------
__device__ __forceinline__ void red_add_h8(uint4* addr, uint4 v) {
    asm volatile("red.global.add.noftz.v4.f16x2 [%0], {%1,%2,%3,%4};"
                 :: "l"(addr), "r"(v.x), "r"(v.y), "r"(v.z), "r"(v.w) : "memory");
}
__device__ __forceinline__ void red_add_h4(uint2* addr, uint2 v) {
    asm volatile("red.global.add.noftz.v2.f16x2 [%0], {%1,%2};"
                 :: "l"(addr), "r"(v.x), "r"(v.y) : "memory");
}
__device__ __forceinline__ void red_add_f2(float* addr, float a, float b) {
    asm volatile("red.global.add.v2.f32 [%0], {%1,%2};"
                 :: "l"(addr), "f"(a), "f"(b) : "memory");
}
__device__ __forceinline__ float leaky(float t) { return t >= 0.f ? t : NEG * t; }

typedef unsigned long long u64t;
__device__ __forceinline__ u64t pk2(float a, float b) {
    u64t r; asm("mov.b64 %0,{%1,%2};" : "=l"(r) : "f"(a), "f"(b)); return r;
}
__device__ __forceinline__ void fma2(u64t& a, u64t x, u64t y) {
    asm("fma.rn.f32x2 %0,%1,%2,%0;" : "+l"(a) : "l"(x), "l"(y));
}
__device__ __forceinline__ void upk2(u64t d, float& a, float& b) {
    asm("mov.b64 {%0,%1},%2;" : "=f"(a), "=f"(b) : "l"(d));
}
__device__ __forceinline__ unsigned h2u(__half2 h) { return *reinterpret_cast<unsigned*>(&h); }
__device__ __forceinline__ float2 u2f2(unsigned u) {
    __half2 h = *reinterpret_cast<__half2*>(&u);
    return __half22float2(h);
}

// ---------------- K0: build f16 verts, zero g_sah / g_acc ----------------
__global__ void k_prep(const float* __restrict__ verts) {
    int i = blockIdx.x * blockDim.x + threadIdx.x;
    int stride = gridDim.x * blockDim.x;
    for (int v = i; v < V_TOTAL; v += stride) {
        float x = verts[3 * v + 0], y = verts[3 * v + 1], z = verts[3 * v + 2];
        g_vph[v] = make_uint2(h2u(__floats2half2_rn(x, y)), h2u(__floats2half2_rn(z, 1.f)));
        g_sah[v] = make_uint2(0u, 0u);
    }
    if (i < BATCH * NOUT) g_acc[i] = 0.f;
}

// ---------------- K0b: convert fc2 weights to f16 h2-pairs ----------------
__global__ void k_w2h(const float* __restrict__ w2) {
    int i = blockIdx.x * blockDim.x + threadIdx.x;
    if (i >= NOUT * KH) return;
    float2 f = *(const float2*)(w2 + 2 * (size_t)i);
    g_w2h2[i] = h2u(__floats2half2_rn(f.x, f.y));
}

// ---------------- K1: scatter verts+degree (f16, 8B rows, separate dest array) ----------------
__global__ void k_scatter_a(const int2* __restrict__ edges) {
    int e = blockIdx.x * blockDim.x + threadIdx.x;
    if (e >= E_TOTAL) return;
    int2 ij = __ldcs(edges + e);
    uint2 vi = __ldg(g_vph + ij.x);
    uint2 vj = __ldg(g_vph + ij.y);
    red_add_h4(g_sah + ij.x, vj);
    red_add_h4(g_sah + ij.y, vi);
}

// ---------------- K2: x1 = leaky(...) -> f16 rows; zero g_sbh ----------------
__global__ void k_x1(const float* __restrict__ verts,
                     const float* __restrict__ w0a, const float* __restrict__ b0a,
                     const float* __restrict__ w1a, const float* __restrict__ b1a) {
    int v = blockIdx.x * blockDim.x + threadIdx.x;
    if (v >= V_TOTAL) return;
    float p0 = verts[3 * v + 0], p1 = verts[3 * v + 1], p2 = verts[3 * v + 2];
    uint2 sr = g_sah[v];
    float2 sxy = u2f2(sr.x), szd = u2f2(sr.y);   // {sum_x,sum_y},{sum_z,degree}
    float o[5];
#pragma unroll
    for (int m = 0; m < 5; m++) {
        float t = __ldg(b0a + m) + szd.y * __ldg(b1a + m);
        t += p0 * __ldg(w0a + 3 * m + 0) + p1 * __ldg(w0a + 3 * m + 1) + p2 * __ldg(w0a + 3 * m + 2);
        t += sxy.x * __ldg(w1a + 3 * m + 0) + sxy.y * __ldg(w1a + 3 * m + 1) + szd.x * __ldg(w1a + 3 * m + 2);
        o[m] = leaky(t);
    }
    uint4 row;
    row.x = h2u(__floats2half2_rn(o[0], o[1]));
    row.y = h2u(__floats2half2_rn(o[2], o[3]));
    row.z = h2u(__floats2half2_rn(o[4], szd.y));
    row.w = 0u;
    g_x1h[v] = row;
    g_sbh[v] = make_uint4(0u, 0u, 0u, 0u);
}

// ---------------- K3: scatter x1 (f16, separate dest array) ----------------
__global__ void k_scatter_b(const int2* __restrict__ edges) {
    int e = blockIdx.x * blockDim.x + threadIdx.x;
    if (e >= E_TOTAL) return;
    int2 ij = __ldcs(edges + e);
    uint4 xi = __ldg(g_x1h + ij.x);
    uint4 xj = __ldg(g_x1h + ij.y);
    red_add_h8(g_sbh + ij.x, xj);
    red_add_h8(g_sbh + ij.y, xi);
}

// ---------------- K4: fused layer-b + fc1, packed f32x2, f16 output ----------------
__global__ __launch_bounds__(256)
void k_vertex(const float* __restrict__ w0b, const float* __restrict__ b0b,
              const float* __restrict__ w1b, const float* __restrict__ b1b,
              const float* __restrict__ fc1w, const float* __restrict__ fc1b) {
    __shared__ u64t s_w0d[100], s_w1d[100], s_b0d[20], s_b1d[20], s_f1d[200];
    __shared__ float s_f1b[16];
    int tid = threadIdx.x;
    if (tid < 100) { float a = w0b[tid], b = w1b[tid]; s_w0d[tid] = pk2(a, a); s_w1d[tid] = pk2(b, b); }
    if (tid < 20)  { float a = b0b[tid], b = b1b[tid]; s_b0d[tid] = pk2(a, a); s_b1d[tid] = pk2(b, b); }
    if (tid < 200) { float f = fc1w[tid]; s_f1d[tid] = pk2(f, f); }
    if (tid < 10)  s_f1b[tid] = fc1b[tid];
    __syncthreads();

    int base = (blockIdx.x * blockDim.x + threadIdx.x) * 4;
    if (base >= V_TOTAL) return;

    float x1[4][5], sb[4][5], deg[4];
#pragma unroll
    for (int u = 0; u < 4; u++) {
        int v = base + u;
        uint4 xr = g_x1h[v];
        float2 f;
        f = u2f2(xr.x); x1[u][0] = f.x; x1[u][1] = f.y;
        f = u2f2(xr.y); x1[u][2] = f.x; x1[u][3] = f.y;
        f = u2f2(xr.z); x1[u][4] = f.x; deg[u] = f.y;
        uint4 srr = g_sbh[v];
        f = u2f2(srr.x); sb[u][0] = f.x; sb[u][1] = f.y;
        f = u2f2(srr.y); sb[u][2] = f.x; sb[u][3] = f.y;
        f = u2f2(srr.z); sb[u][4] = f.x;
    }
    u64t x1p[2][5], sbp[2][5], degp[2];
#pragma unroll
    for (int m = 0; m < 5; m++) {
        x1p[0][m] = pk2(x1[0][m], x1[1][m]); x1p[1][m] = pk2(x1[2][m], x1[3][m]);
        sbp[0][m] = pk2(sb[0][m], sb[1][m]); sbp[1][m] = pk2(sb[2][m], sb[3][m]);
    }
    degp[0] = pk2(deg[0], deg[1]); degp[1] = pk2(deg[2], deg[3]);

    u64t yac[10][2];
#pragma unroll
    for (int q = 0; q < 10; q++) {
        float bq = s_f1b[q];
        yac[q][0] = pk2(bq, bq);
        yac[q][1] = pk2(bq, bq);
    }

#pragma unroll
    for (int n = 0; n < 20; n++) {
        u64t t0 = s_b0d[n], t1 = t0;
        u64t b1d = s_b1d[n];
        fma2(t0, degp[0], b1d);
        fma2(t1, degp[1], b1d);
#pragma unroll
        for (int m = 0; m < 5; m++) {
            u64t w0 = s_w0d[5 * n + m], w1 = s_w1d[5 * n + m];
            fma2(t0, x1p[0][m], w0); fma2(t0, sbp[0][m], w1);
            fma2(t1, x1p[1][m], w0); fma2(t1, sbp[1][m], w1);
        }
        float a, b, c, d;
        upk2(t0, a, b); upk2(t1, c, d);
        u64t xp0 = pk2(leaky(a), leaky(b));
        u64t xp1 = pk2(leaky(c), leaky(d));
#pragma unroll
        for (int q = 0; q < 10; q++) {
            u64t fw2 = s_f1d[20 * q + n];
            fma2(yac[q][0], xp0, fw2);
            fma2(yac[q][1], xp1, fw2);
        }
    }

    float yf[40];
#pragma unroll
    for (int q = 0; q < 10; q++) {
        float a, b;
        upk2(yac[q][0], a, b); yf[q] = leaky(a); yf[10 + q] = leaky(b);
        upk2(yac[q][1], a, b); yf[20 + q] = leaky(a); yf[30 + q] = leaky(b);
    }
    unsigned yo2[20];
#pragma unroll
    for (int t = 0; t < 20; t++) yo2[t] = h2u(__floats2half2_rn(yf[2 * t], yf[2 * t + 1]));
    uint4* dst = (uint4*)(g_yh2 + (size_t)base * 5);
#pragma unroll
    for (int t = 0; t < 5; t++)
        dst[t] = make_uint4(yo2[4 * t], yo2[4 * t + 1], yo2[4 * t + 2], yo2[4 * t + 3]);
}

// ---------------- K5: fc2 via mma m16n8k16, smem-staged B, 2 blocks/SM ----------------
#define KS 296
__global__ __launch_bounds__(256)
void k_fc2mma() {
    __shared__ unsigned sB[64 * 12];                    // [n-row][8 h + pad4]
    const int steps_total = (K2DIM + 15) / 16;          // 3657
    const int per = (steps_total + KS - 1) / KS;        // 13
    int s0 = blockIdx.x * per;
    int s1 = min(s0 + per, steps_total);
    if (s0 >= s1) return;

    int tid = threadIdx.x;
    int warp = tid >> 5, l = tid & 31;
    int m0 = warp * 32;                                 // 8 warps cover M=256
    int r = l >> 2;
    int c0 = (l & 3) * 2;
    int hq = l & 3;                                     // h0 offset within step

    float acc[2][8][4];
#pragma unroll
    for (int mt = 0; mt < 2; mt++)
#pragma unroll
        for (int nt = 0; nt < 8; nt++)
#pragma unroll
            for (int q = 0; q < 4; q++) acc[mt][nt][q] = 0.f;

    const unsigned* ya = g_yh2;
    const unsigned* wa = g_w2h2;
    // B loader indices: 512 elems = 64 rows x 8 h; thread handles e and e+256
    int eRow0 = tid >> 3, eH0 = tid & 7;
    int eRow1 = (tid + 256) >> 3, eH1 = (tid + 256) & 7;

    for (int s = s0; s < s1; s++) {
        int hbase = s * 8;                               // h2-index base of this k16 step
        // ---- stage B tile ----
        __syncthreads();
        {
            int h0g = hbase + eH0, h1g = hbase + eH1;
            sB[eRow0 * 12 + eH0] = (h0g < KH) ? __ldg(wa + (size_t)eRow0 * KH + h0g) : 0u;
            sB[eRow1 * 12 + eH1] = (h1g < KH) ? __ldg(wa + (size_t)eRow1 * KH + h1g) : 0u;
        }
        // ---- A fragments from global (8 independent loads) ----
        int h0 = hbase + hq, h1 = h0 + 4;
        bool g0 = h0 < KH, g1 = h1 < KH;
        unsigned a[2][4];
#pragma unroll
        for (int mt = 0; mt < 2; mt++) {
            size_t rowA = (size_t)(m0 + mt * 16 + r) * KH;
            size_t rowB = rowA + (size_t)8 * KH;
            a[mt][0] = g0 ? __ldg(ya + rowA + h0) : 0u;
            a[mt][1] = g0 ? __ldg(ya + rowB + h0) : 0u;
            a[mt][2] = g1 ? __ldg(ya + rowA + h1) : 0u;
            a[mt][3] = g1 ? __ldg(ya + rowB + h1) : 0u;
        }
        __syncthreads();
#pragma unroll
        for (int mt = 0; mt < 2; mt++)
#pragma unroll
            for (int nt = 0; nt < 8; nt++) {
                unsigned b0 = sB[(nt * 8 + r) * 12 + hq];
                unsigned b1 = sB[(nt * 8 + r) * 12 + 4 + hq];
                asm volatile(
                    "mma.sync.aligned.m16n8k16.row.col.f32.f16.f16.f32 "
                    "{%0,%1,%2,%3}, {%4,%5,%6,%7}, {%8,%9}, {%0,%1,%2,%3};"
                    : "+f"(acc[mt][nt][0]), "+f"(acc[mt][nt][1]),
                      "+f"(acc[mt][nt][2]), "+f"(acc[mt][nt][3])
                    : "r"(a[mt][0]), "r"(a[mt][1]), "r"(a[mt][2]), "r"(a[mt][3]),
                      "r"(b0), "r"(b1));
            }
    }

#pragma unroll
    for (int mt = 0; mt < 2; mt++)
#pragma unroll
        for (int nt = 0; nt < 8; nt++) {
            int row = m0 + mt * 16 + r;
            int col = nt * 8 + c0;
            red_add_f2(&g_acc[row * NOUT + col], acc[mt][nt][0], acc[mt][nt][1]);
            red_add_f2(&g_acc[(row + 8) * NOUT + col], acc[mt][nt][2], acc[mt][nt][3]);
        }
}

// ---------------- K6: bias + softmax ----------------
__global__ void k_softmax(const float* __restrict__ fc2b, float* __restrict__ out) {
    int b = blockIdx.x * 8 + (threadIdx.x >> 5);
    int lane = threadIdx.x & 31;
    if (b >= BATCH) return;
    float v0 = g_acc[b * 64 + lane]      + __ldg(fc2b + lane);
    float v1 = g_acc[b * 64 + 32 + lane] + __ldg(fc2b + 32 + lane);
    float m = fmaxf(v0, v1);
#pragma unroll
    for (int o = 16; o; o >>= 1) m = fmaxf(m, __shfl_xor_sync(0xffffffffu, m, o));
    float e0 = expf(v0 - m), e1 = expf(v1 - m);
    float s = e0 + e1;
#pragma unroll
    for (int o = 16; o; o >>= 1) s += __shfl_xor_sync(0xffffffffu, s, o);
    float inv = 1.f / s;
    out[b * 64 + lane]      = e0 * inv;
    out[b * 64 + 32 + lane] = e1 * inv;
}

// ---------------- launch ----------------
extern "C" void kernel_launch(void* const* d_in, const int* in_sizes, int n_in,
                              void* d_out, int out_size) {
    const float* verts = (const float*)d_in[0];
    const int2*  edges = (const int2*)d_in[1];
    const float* w0a  = (const float*)d_in[2];
    const float* b0a  = (const float*)d_in[3];
    const float* w1a  = (const float*)d_in[4];
    const float* b1a  = (const float*)d_in[5];
    const float* w0b  = (const float*)d_in[6];
    const float* b0b  = (const float*)d_in[7];
    const float* w1b  = (const float*)d_in[8];
    const float* b1b  = (const float*)d_in[9];
    const float* fc1w = (const float*)d_in[10];
    const float* fc1b = (const float*)d_in[11];
    const float* fc2w = (const float*)d_in[12];
    const float* fc2b = (const float*)d_in[13];

    k_prep<<<4096, 256>>>(verts);
    k_w2h<<<(NOUT * KH + 255) / 256, 256>>>(fc2w);
    k_scatter_a<<<(E_TOTAL + 255) / 256, 256>>>(edges);
    k_x1<<<(V_TOTAL + 255) / 256, 256>>>(verts, w0a, b0a, w1a, b1a);
    k_scatter_b<<<(E_TOTAL + 255) / 256, 256>>>(edges);
    k_vertex<<<(V_TOTAL / 4 + 255) / 256, 256>>>(w0b, b0b, w1b, b1b, fc1w, fc1b);
    k_fc2mma<<<KS, 256>>>();
    k_softmax<<<32, 256>>>(fc2b, (float*)d_out);
}